// round 4
// baseline (speedup 1.0000x reference)
#include <cuda_runtime.h>

// SSIM loss, B=64, 1x512x512 fp32, 11x11 box filter, zero padding.
// R3: latency-bound fix (issue=31.5%, occ=10.4%, no pipe saturated).
// Column-split: each 32-row strip handled by 2 warps x 8 cols/lane.
// Same total work; half the register state; 1024 CTAs x 64 thr -> 2x warps/SM.
// Seam halo between the warp pair via parity-double-buffered smem.

typedef unsigned long long u64;

__device__ __forceinline__ u64 pk2(float lo, float hi) {
    u64 r; asm("mov.b64 %0, {%1, %2};" : "=l"(r) : "f"(lo), "f"(hi)); return r;
}
__device__ __forceinline__ void upk2(u64 v, float& lo, float& hi) {
    asm("mov.b64 {%0, %1}, %2;" : "=f"(lo), "=f"(hi) : "l"(v));
}
__device__ __forceinline__ u64 add2(u64 a, u64 b) {
    u64 r; asm("add.rn.f32x2 %0, %1, %2;" : "=l"(r) : "l"(a), "l"(b)); return r;
}
__device__ __forceinline__ u64 mul2(u64 a, u64 b) {
    u64 r; asm("mul.rn.f32x2 %0, %1, %2;" : "=l"(r) : "l"(a), "l"(b)); return r;
}
__device__ __forceinline__ u64 fma2(u64 a, u64 b, u64 c) {
    u64 r; asm("fma.rn.f32x2 %0, %1, %2, %3;" : "=l"(r) : "l"(a), "l"(b), "l"(c)); return r;
}

namespace {
constexpr int Hh = 512;
constexpr int Ww = 512;
constexpr int Bb = 64;
constexpr int CHUNK = 32;                  // output rows per strip
constexpr int NCHUNK = Hh / CHUNK;         // 16
constexpr int BLK = 64;                    // 2 warps/CTA, one strip/CTA
constexpr int NCTA = Bb * NCHUNK;          // 1024
// SSIM rescaled by S^4, S=121: C1*S^2, C2*S^2
constexpr float C1S = 0.0001f * 14641.0f;  // 1.4641
constexpr float C2S = 0.0009f * 14641.0f;  // 13.1769
}

__device__ double g_acc;       // zero at load; restored by last CTA each replay
__device__ int    g_count;

__global__ void __launch_bounds__(BLK)
k_ssim(const float* __restrict__ X, const float* __restrict__ Y, float* __restrict__ out) {
    const int warp  = threadIdx.x >> 5;        // 0: cols [0,256), 1: cols [256,512)
    const int lane  = threadIdx.x & 31;
    const int batch = blockIdx.x >> 4;         // / NCHUNK
    const int chunk = blockIdx.x & (NCHUNK - 1);
    const int row0  = chunk * CHUNK;
    const int c0    = warp * 256 + lane * 8;   // 8 cols per lane
    const float* xb = X + batch * (Hh * Ww) + c0;
    const float* yb = Y + batch * (Hh * Ww) + c0;

    // seam exchange: [dir][parity][j]; dir 0 = warp0->warp1 (left halo of col 256),
    // dir 1 = warp1->warp0 (right halo of col 255)
    __shared__ u64   s_ab[2][2][5];
    __shared__ u64   s_sq[2][2][5];
    __shared__ float s_xy[2][2][5];
    __shared__ float s_red[2];

    const u64 KN1 = pk2(-1.f, -1.f);

    // per-column running sums: packed (sx,sy), packed (sxx,syy), scalar sxy
    u64 vab[8], vsq[8];
    float vxy[8];
#pragma unroll
    for (int k = 0; k < 8; k++) { vab[k] = 0ull; vsq[k] = 0ull; vxy[k] = 0.f; }

    const int lvmin = (row0 - 5 > 0) ? (row0 - 5) : 0;
    float acc = 0.f;

#define VENT(k, xs, ys) do { float _x=(xs), _y=(ys); u64 _p=pk2(_x,_y); \
    vab[k]=add2(vab[k],_p); vsq[k]=fma2(_p,_p,vsq[k]); vxy[k]=fmaf(_x,_y,vxy[k]); } while(0)
#define VLEA(k, xs, ys) do { float _x=(xs), _y=(ys); u64 _p=pk2(_x,_y); u64 _n=mul2(_p,KN1); \
    vab[k]=add2(vab[k],_n); vsq[k]=fma2(_n,_p,vsq[k]); vxy[k]=fmaf(-_x,_y,vxy[k]); } while(0)
#define ROW_APPLY(OP) \
    OP(0,a0.x,b0.x); OP(1,a0.y,b0.y); OP(2,a0.z,b0.z); OP(3,a0.w,b0.w); \
    OP(4,a1.x,b1.x); OP(5,a1.y,b1.y); OP(6,a1.z,b1.z); OP(7,a1.w,b1.w);

    for (int ri = row0 - 5; ri <= row0 + CHUNK + 4; ++ri) {
        if (ri >= 0 && ri < Hh) {                      // entering row
            const float4* xr = reinterpret_cast<const float4*>(xb + ri * Ww);
            const float4* yr = reinterpret_cast<const float4*>(yb + ri * Ww);
            float4 a0 = xr[0], a1 = xr[1];
            float4 b0 = yr[0], b1 = yr[1];
            ROW_APPLY(VENT)
        }
        const int lv = ri - 11;                        // leaving row
        if (lv >= lvmin) {
            const float4* xr = reinterpret_cast<const float4*>(xb + lv * Ww);
            const float4* yr = reinterpret_cast<const float4*>(yb + lv * Ww);
            float4 a0 = xr[0], a1 = xr[1];
            float4 b0 = yr[0], b1 = yr[1];
            ROW_APPLY(VLEA)
        }
        if (ri >= row0 + 5) {                          // emit output row ri-5
            const int par = ri & 1;
            // seam publish (one lane per warp)
            if (threadIdx.x == 31) {                   // warp0 lane31: cols 251..255
#pragma unroll
                for (int j = 0; j < 5; j++) {
                    s_ab[0][par][j] = vab[3 + j];
                    s_sq[0][par][j] = vsq[3 + j];
                    s_xy[0][par][j] = vxy[3 + j];
                }
            } else if (threadIdx.x == 32) {            // warp1 lane0: cols 256..260
#pragma unroll
                for (int j = 0; j < 5; j++) {
                    s_ab[1][par][j] = vab[j];
                    s_sq[1][par][j] = vsq[j];
                    s_xy[1][par][j] = vxy[j];
                }
            }
            __syncthreads();

            // halos: left = lane-1 cols 3..7, right = lane+1 cols 0..4
            u64 lab[5], lsq[5], rab[5], rsq[5];
            float lxy[5], rxy[5];
#pragma unroll
            for (int j = 0; j < 5; j++) {
                lab[j] = __shfl_up_sync(0xffffffffu, vab[3 + j], 1);
                lsq[j] = __shfl_up_sync(0xffffffffu, vsq[3 + j], 1);
                lxy[j] = __shfl_up_sync(0xffffffffu, vxy[3 + j], 1);
                rab[j] = __shfl_down_sync(0xffffffffu, vab[j], 1);
                rsq[j] = __shfl_down_sync(0xffffffffu, vsq[j], 1);
                rxy[j] = __shfl_down_sync(0xffffffffu, vxy[j], 1);
            }
            if (lane == 0) {
#pragma unroll
                for (int j = 0; j < 5; j++) {
                    if (warp == 0) { lab[j] = 0ull; lsq[j] = 0ull; lxy[j] = 0.f; }
                    else { lab[j] = s_ab[0][par][j]; lsq[j] = s_sq[0][par][j]; lxy[j] = s_xy[0][par][j]; }
                }
            }
            if (lane == 31) {
#pragma unroll
                for (int j = 0; j < 5; j++) {
                    if (warp == 1) { rab[j] = 0ull; rsq[j] = 0ull; rxy[j] = 0.f; }
                    else { rab[j] = s_ab[1][par][j]; rsq[j] = s_sq[1][par][j]; rxy[j] = s_xy[1][par][j]; }
                }
            }

            // window init for local col 0: l[0..4] + v[0..5]
#define HIN2(L, V) add2(add2(add2(add2(L[0],L[1]), add2(L[2],L[3])), \
                             add2(add2(L[4],V[0]), add2(V[1],V[2]))), \
                        add2(add2(V[3],V[4]), V[5]))
            u64 sab = HIN2(lab, vab);
            u64 ssq = HIN2(lsq, vsq);
            float sxy = ((lxy[0]+lxy[1]) + (lxy[2]+lxy[3])) + ((lxy[4]+vxy[0]) + (vxy[1]+vxy[2]))
                      + ((vxy[3]+vxy[4]) + vxy[5]);
#undef HIN2
            // sliding over 8 local cols: add v[j+6] (j<=1) / r[j-2]; sub l[j] (j<5) / v[j-5]
#define HADD(A, R) ((j + 6 <= 7) ? A[(j + 6) & 7] : R[j - 2])
#define HSUB(A, L) ((j >= 5) ? A[(j - 5) & 7] : L[j])
#pragma unroll
            for (int j = 0; j < 8; j++) {
                float sx, sy, sxx, syy;
                upk2(sab, sx, sy);
                upk2(ssq, sxx, syy);
                float pxy = sx * sy;
                float qx, qy;
                upk2(mul2(sab, sab), qx, qy);
                float m2   = qx + qy;                    // sx^2 + sy^2
                float esum = sxx + syy;
                float t1   = fmaf(2.f, pxy, C1S);
                float t2   = fmaf(242.f, sxy, fmaf(-2.f, pxy, C2S));
                float num  = t1 * t2;
                float den1 = m2 + C1S;
                float den2 = fmaf(121.f, esum, C2S - m2);
                acc += __fdividef(num, den1 * den2);
                if (j < 7) {
                    sab = add2(sab, HADD(vab, rab));
                    sab = fma2(HSUB(vab, lab), KN1, sab);
                    ssq = add2(ssq, HADD(vsq, rsq));
                    ssq = fma2(HSUB(vsq, lsq), KN1, ssq);
                    sxy += HADD(vxy, rxy) - HSUB(vxy, lxy);
                }
            }
#undef HADD
#undef HSUB
        }
    }

    // reduce: warp shuffle -> smem -> one double atomic per CTA
#pragma unroll
    for (int off = 16; off; off >>= 1)
        acc += __shfl_xor_sync(0xffffffffu, acc, off);
    if (lane == 0) s_red[warp] = acc;
    __syncthreads();
    if (threadIdx.x == 0) {
        atomicAdd(&g_acc, (double)(s_red[0] + s_red[1]));
        __threadfence();
        int old = atomicAdd(&g_count, 1);
        if (old == NCTA - 1) {
            double total = g_acc;
            out[0] = (float)(1.0 - total * (1.0 / ((double)Bb * Hh * Ww)));
            g_acc = 0.0;
            g_count = 0;
        }
    }
}

extern "C" void kernel_launch(void* const* d_in, const int* in_sizes, int n_in,
                              void* d_out, int out_size) {
    const float* x = (const float*)d_in[0];
    const float* y = (const float*)d_in[1];
    (void)in_sizes; (void)n_in; (void)out_size;
    k_ssim<<<NCTA, BLK>>>(x, y, (float*)d_out);
}

// round 5
// speedup vs baseline: 1.3384x; 1.3384x over previous
#include <cuda_runtime.h>

// SSIM loss, B=64, 1x512x512 fp32, 11x11 box filter, zero padding.
// R4: back to 16 cols/lane (R3's 8-col split added per-pixel overhead).
// Fixes vs R2:
//  - 1024 single-warp CTAs (was 256x128: 108 SMs got 2 CTAs, 40 got 1 -> ~1.7x
//    wave imbalance). Now ~7 CTAs/SM everywhere, no __syncthreads at all.
//  - branch-free phase-peeled loops (warmup/first/steady/tail, specialized for
//    top/interior/bottom chunks) so ptxas can software-pipeline the 16 LDG.128s.
//  - direct u64 shuffles in halo exchange (drops pack/unpack movs).

typedef unsigned long long u64;

__device__ __forceinline__ u64 pk2(float lo, float hi) {
    u64 r; asm("mov.b64 %0, {%1, %2};" : "=l"(r) : "f"(lo), "f"(hi)); return r;
}
__device__ __forceinline__ void upk2(u64 v, float& lo, float& hi) {
    asm("mov.b64 {%0, %1}, %2;" : "=f"(lo), "=f"(hi) : "l"(v));
}
__device__ __forceinline__ u64 add2(u64 a, u64 b) {
    u64 r; asm("add.rn.f32x2 %0, %1, %2;" : "=l"(r) : "l"(a), "l"(b)); return r;
}
__device__ __forceinline__ u64 mul2(u64 a, u64 b) {
    u64 r; asm("mul.rn.f32x2 %0, %1, %2;" : "=l"(r) : "l"(a), "l"(b)); return r;
}
__device__ __forceinline__ u64 fma2(u64 a, u64 b, u64 c) {
    u64 r; asm("fma.rn.f32x2 %0, %1, %2, %3;" : "=l"(r) : "l"(a), "l"(b), "l"(c)); return r;
}

namespace {
constexpr int Hh = 512;
constexpr int Ww = 512;
constexpr int Bb = 64;
constexpr int CHUNK = 32;                  // output rows per warp
constexpr int NCHUNK = Hh / CHUNK;         // 16
constexpr int NCTA = Bb * NCHUNK;          // 1024 single-warp CTAs
// SSIM rescaled by S^4, S=121: C1*S^2, C2*S^2
constexpr float C1S = 0.0001f * 14641.0f;  // 1.4641
constexpr float C2S = 0.0009f * 14641.0f;  // 13.1769
}

__device__ double g_acc;       // zero at load; restored by last CTA each replay
__device__ int    g_count;

__global__ void __launch_bounds__(32)
k_ssim(const float* __restrict__ X, const float* __restrict__ Y, float* __restrict__ out) {
    const int lane  = threadIdx.x;             // 32-thread CTA = 1 warp
    const int batch = blockIdx.x >> 4;         // / NCHUNK
    const int chunk = blockIdx.x & (NCHUNK - 1);
    const int row0  = chunk * CHUNK;
    const int c0    = lane << 4;               // 16 cols per lane; warp = full row
    const float* xb = X + batch * (Hh * Ww) + c0;
    const float* yb = Y + batch * (Hh * Ww) + c0;

    const u64 KN1 = pk2(-1.f, -1.f);
    const float lmask = (lane == 0)  ? 0.f : 1.f;
    const float rmask = (lane == 31) ? 0.f : 1.f;
    const u64 lmask2 = pk2(lmask, lmask);
    const u64 rmask2 = pk2(rmask, rmask);

    // per-column running sums: packed (sx,sy), packed (sxx,syy), scalar sxy
    u64 vab[16], vsq[16];
    float vxy[16];
#pragma unroll
    for (int k = 0; k < 16; k++) { vab[k] = 0ull; vsq[k] = 0ull; vxy[k] = 0.f; }

    float acc = 0.f;

#define VENT(k, xs, ys) do { float _x=(xs), _y=(ys); u64 _p=pk2(_x,_y); \
    vab[k]=add2(vab[k],_p); vsq[k]=fma2(_p,_p,vsq[k]); vxy[k]=fmaf(_x,_y,vxy[k]); } while(0)
#define VLEA(k, xs, ys) do { float _x=(xs), _y=(ys); u64 _p=pk2(_x,_y); u64 _n=mul2(_p,KN1); \
    vab[k]=add2(vab[k],_n); vsq[k]=fma2(_n,_p,vsq[k]); vxy[k]=fmaf(-_x,_y,vxy[k]); } while(0)
#define ROW_APPLY(OP) \
    OP(0,a0.x,b0.x);  OP(1,a0.y,b0.y);  OP(2,a0.z,b0.z);  OP(3,a0.w,b0.w); \
    OP(4,a1.x,b1.x);  OP(5,a1.y,b1.y);  OP(6,a1.z,b1.z);  OP(7,a1.w,b1.w); \
    OP(8,a2.x,b2.x);  OP(9,a2.y,b2.y);  OP(10,a2.z,b2.z); OP(11,a2.w,b2.w); \
    OP(12,a3.x,b3.x); OP(13,a3.y,b3.y); OP(14,a3.z,b3.z); OP(15,a3.w,b3.w);

#define ENTER(r) do { \
    const float4* xr = reinterpret_cast<const float4*>(xb + (r) * Ww); \
    const float4* yr = reinterpret_cast<const float4*>(yb + (r) * Ww); \
    float4 a0 = xr[0], a1 = xr[1], a2 = xr[2], a3 = xr[3]; \
    float4 b0 = yr[0], b1 = yr[1], b2 = yr[2], b3 = yr[3]; \
    ROW_APPLY(VENT) } while(0)

#define LEAVE(r) do { \
    const float4* xr = reinterpret_cast<const float4*>(xb + (r) * Ww); \
    const float4* yr = reinterpret_cast<const float4*>(yb + (r) * Ww); \
    float4 a0 = xr[0], a1 = xr[1], a2 = xr[2], a3 = xr[3]; \
    float4 b0 = yr[0], b1 = yr[1], b2 = yr[2], b3 = yr[3]; \
    ROW_APPLY(VLEA) } while(0)

#define HIN2(L, V) add2(add2(add2(add2(L[0],L[1]), add2(L[2],L[3])), \
                             add2(add2(L[4],V[0]), add2(V[1],V[2]))), \
                        add2(add2(V[3],V[4]), V[5]))
#define HADD(A, R) ((j + 6 <= 15) ? A[(j + 6) & 15] : R[((j - 10) < 0) ? 0 : (j - 10)])
#define HSUB(A, L) ((j >= 5) ? A[(j - 5) & 15] : L[(j < 5) ? j : 4])

#define EPI() do { \
    u64 lab[5], lsq[5], rab[5], rsq[5]; \
    float lxy[5], rxy[5]; \
    _Pragma("unroll") \
    for (int j = 0; j < 5; j++) { \
        lab[j] = mul2(__shfl_up_sync(0xffffffffu, vab[11 + j], 1), lmask2); \
        lsq[j] = mul2(__shfl_up_sync(0xffffffffu, vsq[11 + j], 1), lmask2); \
        lxy[j] = __shfl_up_sync(0xffffffffu, vxy[11 + j], 1) * lmask; \
        rab[j] = mul2(__shfl_down_sync(0xffffffffu, vab[j], 1), rmask2); \
        rsq[j] = mul2(__shfl_down_sync(0xffffffffu, vsq[j], 1), rmask2); \
        rxy[j] = __shfl_down_sync(0xffffffffu, vxy[j], 1) * rmask; \
    } \
    u64 sab = HIN2(lab, vab); \
    u64 ssq = HIN2(lsq, vsq); \
    float sxy = ((lxy[0]+lxy[1]) + (lxy[2]+lxy[3])) + ((lxy[4]+vxy[0]) + (vxy[1]+vxy[2])) \
              + ((vxy[3]+vxy[4]) + vxy[5]); \
    _Pragma("unroll") \
    for (int j = 0; j < 16; j++) { \
        float sx, sy, sxx, syy; \
        upk2(sab, sx, sy); \
        upk2(ssq, sxx, syy); \
        float pxy = sx * sy; \
        float qx, qy; \
        upk2(mul2(sab, sab), qx, qy); \
        float m2   = qx + qy; \
        float esum = sxx + syy; \
        float t1   = fmaf(2.f, pxy, C1S); \
        float t2   = fmaf(242.f, sxy, fmaf(-2.f, pxy, C2S)); \
        float num  = t1 * t2; \
        float den1 = m2 + C1S; \
        float den2 = fmaf(121.f, esum, C2S - m2); \
        acc += __fdividef(num, den1 * den2); \
        if (j < 15) { \
            sab = add2(sab, HADD(vab, rab)); \
            sab = fma2(HSUB(vab, lab), KN1, sab); \
            ssq = add2(ssq, HADD(vsq, rsq)); \
            ssq = fma2(HSUB(vsq, lsq), KN1, ssq); \
            sxy += HADD(vxy, rxy) - HSUB(vxy, lxy); \
        } \
    } } while(0)

    if (chunk == 0) {
        // top: warmup rows 0..4, first epi at ri=5, no-leave epis 6..10, full 11..36
#pragma unroll
        for (int ri = 0; ri <= 4; ++ri) ENTER(ri);
        ENTER(5); EPI();
#pragma unroll 2
        for (int ri = 6; ri <= 10; ++ri) { ENTER(ri); EPI(); }
#pragma unroll 2
        for (int ri = 11; ri <= 36; ++ri) { ENTER(ri); LEAVE(ri - 11); EPI(); }
    } else if (chunk == NCHUNK - 1) {
        // bottom (row0=480): warmup 475..484, first epi 485, full 486..511,
        // leave-only tail 512..516
#pragma unroll 2
        for (int i = 0; i < 10; ++i) ENTER(row0 - 5 + i);
        ENTER(row0 + 5); EPI();
#pragma unroll 2
        for (int ri = row0 + 6; ri <= Hh - 1; ++ri) { ENTER(ri); LEAVE(ri - 11); EPI(); }
#pragma unroll 2
        for (int ri = Hh; ri <= row0 + CHUNK + 4; ++ri) { LEAVE(ri - 11); EPI(); }
    } else {
        // interior: completely branch-free phases
#pragma unroll 2
        for (int i = 0; i < 10; ++i) ENTER(row0 - 5 + i);
        ENTER(row0 + 5); EPI();
#pragma unroll 2
        for (int i = 0; i < CHUNK - 1; ++i) {
            const int ri = row0 + 6 + i;
            ENTER(ri);
            LEAVE(ri - 11);
            EPI();
        }
    }

    // warp reduce, one double atomic per CTA(=warp)
#pragma unroll
    for (int off = 16; off; off >>= 1)
        acc += __shfl_xor_sync(0xffffffffu, acc, off);
    if (lane == 0) {
        atomicAdd(&g_acc, (double)acc);
        __threadfence();
        int old = atomicAdd(&g_count, 1);
        if (old == NCTA - 1) {
            double total = g_acc;
            out[0] = (float)(1.0 - total * (1.0 / ((double)Bb * Hh * Ww)));
            g_acc = 0.0;
            g_count = 0;
        }
    }
}

extern "C" void kernel_launch(void* const* d_in, const int* in_sizes, int n_in,
                              void* d_out, int out_size) {
    const float* x = (const float*)d_in[0];
    const float* y = (const float*)d_in[1];
    (void)in_sizes; (void)n_in; (void)out_size;
    k_ssim<<<NCTA, 32>>>(x, y, (float*)d_out);
}

// round 6
// speedup vs baseline: 1.5217x; 1.1370x over previous
#include <cuda_runtime.h>

// SSIM loss, B=64, 1x512x512 fp32, 11x11 box filter, zero padding.
// R5: per-warp latency tolerance (profiles show occ~10%, issue~30%, warps
// stalled ~83% -> latency-bound per warp, and MORE warps made it worse).
//  - software prefetch: next row-pair's 16 LDG.128 issued before the current
//    row's ~500cyc epilogue (64 regs of buffer; occupancy is grid-limited so
//    registers are free).
//  - sliding-window serial chain split in two (inits at col 0 and col 8,
//    7 slides each, interleaved) -> 2x ILP on the critical path.
//  - template-specialized top/interior/bottom chunks; steady loop branch-free.
// Shape: R2's best (256 CTAs x 128 thr, CHUNK=32, 16 cols/lane).

typedef unsigned long long u64;

__device__ __forceinline__ u64 pk2(float lo, float hi) {
    u64 r; asm("mov.b64 %0, {%1, %2};" : "=l"(r) : "f"(lo), "f"(hi)); return r;
}
__device__ __forceinline__ void upk2(u64 v, float& lo, float& hi) {
    asm("mov.b64 {%0, %1}, %2;" : "=f"(lo), "=f"(hi) : "l"(v));
}
__device__ __forceinline__ u64 add2(u64 a, u64 b) {
    u64 r; asm("add.rn.f32x2 %0, %1, %2;" : "=l"(r) : "l"(a), "l"(b)); return r;
}
__device__ __forceinline__ u64 mul2(u64 a, u64 b) {
    u64 r; asm("mul.rn.f32x2 %0, %1, %2;" : "=l"(r) : "l"(a), "l"(b)); return r;
}
__device__ __forceinline__ u64 fma2(u64 a, u64 b, u64 c) {
    u64 r; asm("fma.rn.f32x2 %0, %1, %2, %3;" : "=l"(r) : "l"(a), "l"(b), "l"(c)); return r;
}

namespace {
constexpr int Hh = 512;
constexpr int Ww = 512;
constexpr int Bb = 64;
constexpr int CHUNK = 32;
constexpr int NCHUNK = Hh / CHUNK;         // 16
constexpr int BLK = 128;                   // 4 warps/CTA
constexpr int NCTA = Bb * NCHUNK * 32 / BLK; // 256
constexpr float C1S = 0.0001f * 14641.0f;  // 1.4641
constexpr float C2S = 0.0009f * 14641.0f;  // 13.1769
}

__device__ double g_acc;
__device__ int    g_count;

template<bool TOP, bool BOT>
__device__ __forceinline__ float run_chunk(const float* __restrict__ xb,
                                           const float* __restrict__ yb,
                                           const int row0, const int lane) {
    const u64 KN1 = pk2(-1.f, -1.f);
    const float lmaskf = (lane == 0)  ? 0.f : 1.f;
    const float rmaskf = (lane == 31) ? 0.f : 1.f;
    const u64 lmask2 = pk2(lmaskf, lmaskf);
    const u64 rmask2 = pk2(rmaskf, rmaskf);

    u64 vab[16], vsq[16];
    float vxy[16];
#pragma unroll
    for (int k = 0; k < 16; k++) { vab[k] = 0ull; vsq[k] = 0ull; vxy[k] = 0.f; }

    float accA = 0.f, accB = 0.f;
    float4 pex0, pex1, pex2, pex3, pey0, pey1, pey2, pey3;   // prefetched enter row
    float4 plx0, plx1, plx2, plx3, ply0, ply1, ply2, ply3;   // prefetched leave row

#define VENT(k, xs, ys) do { float _x=(xs), _y=(ys); u64 _p=pk2(_x,_y); \
    vab[k]=add2(vab[k],_p); vsq[k]=fma2(_p,_p,vsq[k]); vxy[k]=fmaf(_x,_y,vxy[k]); } while(0)
#define VLEA(k, xs, ys) do { float _x=(xs), _y=(ys); u64 _p=pk2(_x,_y); u64 _n=mul2(_p,KN1); \
    vab[k]=add2(vab[k],_n); vsq[k]=fma2(_n,_p,vsq[k]); vxy[k]=fmaf(-_x,_y,vxy[k]); } while(0)
#define ROW_APPLY(OP) \
    OP(0,a0.x,b0.x);  OP(1,a0.y,b0.y);  OP(2,a0.z,b0.z);  OP(3,a0.w,b0.w); \
    OP(4,a1.x,b1.x);  OP(5,a1.y,b1.y);  OP(6,a1.z,b1.z);  OP(7,a1.w,b1.w); \
    OP(8,a2.x,b2.x);  OP(9,a2.y,b2.y);  OP(10,a2.z,b2.z); OP(11,a2.w,b2.w); \
    OP(12,a3.x,b3.x); OP(13,a3.y,b3.y); OP(14,a3.z,b3.z); OP(15,a3.w,b3.w);

#define ENTER_DIRECT(r) do { \
    const float4* xr = reinterpret_cast<const float4*>(xb + (r) * Ww); \
    const float4* yr = reinterpret_cast<const float4*>(yb + (r) * Ww); \
    float4 a0 = xr[0], a1 = xr[1], a2 = xr[2], a3 = xr[3]; \
    float4 b0 = yr[0], b1 = yr[1], b2 = yr[2], b3 = yr[3]; \
    ROW_APPLY(VENT) } while(0)

#define PREF_E(r) do { \
    const float4* _xr = reinterpret_cast<const float4*>(xb + (r) * Ww); \
    const float4* _yr = reinterpret_cast<const float4*>(yb + (r) * Ww); \
    pex0=_xr[0]; pex1=_xr[1]; pex2=_xr[2]; pex3=_xr[3]; \
    pey0=_yr[0]; pey1=_yr[1]; pey2=_yr[2]; pey3=_yr[3]; } while(0)

#define PREF_L(r) do { \
    const float4* _xr = reinterpret_cast<const float4*>(xb + (r) * Ww); \
    const float4* _yr = reinterpret_cast<const float4*>(yb + (r) * Ww); \
    plx0=_xr[0]; plx1=_xr[1]; plx2=_xr[2]; plx3=_xr[3]; \
    ply0=_yr[0]; ply1=_yr[1]; ply2=_yr[2]; ply3=_yr[3]; } while(0)

#define SC4(v, m) do { (v).x*=(m); (v).y*=(m); (v).z*=(m); (v).w*=(m); } while(0)

    // ---- epilogue: two independent sliding chains (cols 0..7 and 8..15) ----
#define HIN2(L, V) add2(add2(add2(add2(L[0],L[1]), add2(L[2],L[3])), \
                             add2(add2(L[4],V[0]), add2(V[1],V[2]))), \
                        add2(add2(V[3],V[4]), V[5]))
#define SUM11P(V) add2(add2(add2(add2(V[3],V[4]), add2(V[5],V[6])), \
                            add2(add2(V[7],V[8]), add2(V[9],V[10]))), \
                       add2(add2(V[11],V[12]), V[13]))
#define HADD(A, R, jj) (((jj) + 6 <= 15) ? A[((jj) + 6) & 15] : R[(((jj) - 10) < 0) ? 0 : ((jj) - 10)])
#define HSUB(A, L, jj) (((jj) >= 5) ? A[((jj) - 5) & 15] : L[((jj) < 5) ? (jj) : 4])

#define PIX(sab, ssq, sxy, accv) do { \
    float sx, sy, sxx, syy; \
    upk2(sab, sx, sy); \
    upk2(ssq, sxx, syy); \
    float pxy  = sx * sy; \
    float m2   = fmaf(sx, sx, sy * sy); \
    float esum = sxx + syy; \
    float t1   = fmaf(2.f, pxy, C1S); \
    float t2   = fmaf(242.f, sxy, fmaf(-2.f, pxy, C2S)); \
    float num  = t1 * t2; \
    float den  = (m2 + C1S) * fmaf(121.f, esum, C2S - m2); \
    accv += __fdividef(num, den); } while(0)

#define EPI() do { \
    u64 lab[5], lsq[5], rab[5], rsq[5]; \
    float lxy[5], rxy[5]; \
    _Pragma("unroll") \
    for (int j = 0; j < 5; j++) { \
        lab[j] = mul2(__shfl_up_sync(0xffffffffu, vab[11 + j], 1), lmask2); \
        lsq[j] = mul2(__shfl_up_sync(0xffffffffu, vsq[11 + j], 1), lmask2); \
        lxy[j] = __shfl_up_sync(0xffffffffu, vxy[11 + j], 1) * lmaskf; \
        rab[j] = mul2(__shfl_down_sync(0xffffffffu, vab[j], 1), rmask2); \
        rsq[j] = mul2(__shfl_down_sync(0xffffffffu, vsq[j], 1), rmask2); \
        rxy[j] = __shfl_down_sync(0xffffffffu, vxy[j], 1) * rmaskf; \
    } \
    u64 sabA = HIN2(lab, vab); \
    u64 ssqA = HIN2(lsq, vsq); \
    float sxyA = ((lxy[0]+lxy[1]) + (lxy[2]+lxy[3])) + ((lxy[4]+vxy[0]) + (vxy[1]+vxy[2])) \
               + ((vxy[3]+vxy[4]) + vxy[5]); \
    u64 sabB = SUM11P(vab); \
    u64 ssqB = SUM11P(vsq); \
    float sxyB = ((vxy[3]+vxy[4]) + (vxy[5]+vxy[6])) + ((vxy[7]+vxy[8]) + (vxy[9]+vxy[10])) \
               + ((vxy[11]+vxy[12]) + vxy[13]); \
    _Pragma("unroll") \
    for (int j = 0; j < 8; j++) { \
        PIX(sabA, ssqA, sxyA, accA); \
        PIX(sabB, ssqB, sxyB, accB); \
        if (j < 7) { \
            const int jB = j + 8; \
            sabA = add2(sabA, HADD(vab, rab, j)); \
            sabA = fma2(HSUB(vab, lab, j), KN1, sabA); \
            ssqA = add2(ssqA, HADD(vsq, rsq, j)); \
            ssqA = fma2(HSUB(vsq, lsq, j), KN1, ssqA); \
            sxyA += HADD(vxy, rxy, j) - HSUB(vxy, lxy, j); \
            sabB = add2(sabB, HADD(vab, rab, jB)); \
            sabB = fma2(HSUB(vab, lab, jB), KN1, sabB); \
            ssqB = add2(ssqB, HADD(vsq, rsq, jB)); \
            ssqB = fma2(HSUB(vsq, lsq, jB), KN1, ssqB); \
            sxyB += HADD(vxy, rxy, jB) - HSUB(vxy, lxy, jB); \
        } \
    } } while(0)

    // ---- warmup: rows row0-5 .. row0+4 (TOP skips negative rows) ----
    {
        const int w0 = TOP ? 5 : 0;
#pragma unroll
        for (int i = w0; i < 10; i++) ENTER_DIRECT(row0 - 5 + i);
    }

    // ---- first output row (ri = row0+5, no leave) ----
    ENTER_DIRECT(row0 + 5);
    {   // prefetch for steady i=0: enter row0+6, leave row0-5 (clamped for TOP)
        const int er = row0 + 6;
        const int lr = TOP ? 0 : (row0 - 5);
        PREF_E(er);
        PREF_L(lr);
    }
    EPI();

    // ---- steady: 31 iterations, branch-free, prefetched ----
#pragma unroll 1
    for (int i = 0; i < CHUNK - 1; i++) {
        const int ri = row0 + 6 + i;
        const int lv = ri - 11;
        {   // consume prefetched enter
            float4 a0 = pex0, a1 = pex1, a2 = pex2, a3 = pex3;
            float4 b0 = pey0, b1 = pey1, b2 = pey2, b3 = pey3;
            if (BOT) {
                const float em = (ri < Hh) ? 1.f : 0.f;
                SC4(a0, em); SC4(a1, em); SC4(a2, em); SC4(a3, em);
                SC4(b0, em); SC4(b1, em); SC4(b2, em); SC4(b3, em);
            }
            ROW_APPLY(VENT)
        }
        {   // consume prefetched leave
            float4 a0 = plx0, a1 = plx1, a2 = plx2, a3 = plx3;
            float4 b0 = ply0, b1 = ply1, b2 = ply2, b3 = ply3;
            if (TOP) {
                const float lm = (lv >= 0) ? 1.f : 0.f;
                SC4(a0, lm); SC4(a1, lm); SC4(a2, lm); SC4(a3, lm);
                SC4(b0, lm); SC4(b1, lm); SC4(b2, lm); SC4(b3, lm);
            }
            ROW_APPLY(VLEA)
        }
        {   // prefetch next iteration's rows (clamped; garbage never consumed)
            int er = ri + 1; if (BOT && er > Hh - 1) er = Hh - 1;
            int lr = lv + 1; if (TOP && lr < 0) lr = 0;
            PREF_E(er);
            PREF_L(lr);
        }
        EPI();
    }

    return accA + accB;

#undef VENT
#undef VLEA
#undef ROW_APPLY
#undef ENTER_DIRECT
#undef PREF_E
#undef PREF_L
#undef SC4
#undef HIN2
#undef SUM11P
#undef HADD
#undef HSUB
#undef PIX
#undef EPI
}

__global__ void __launch_bounds__(BLK)
k_ssim(const float* __restrict__ X, const float* __restrict__ Y, float* __restrict__ out) {
    const int warp  = threadIdx.x >> 5;
    const int lane  = threadIdx.x & 31;
    const int gwarp = blockIdx.x * (BLK / 32) + warp;
    const int batch = gwarp >> 4;              // / NCHUNK
    const int chunk = gwarp & (NCHUNK - 1);
    const int row0  = chunk * CHUNK;
    const int c0    = lane << 4;
    const float* xb = X + batch * (Hh * Ww) + c0;
    const float* yb = Y + batch * (Hh * Ww) + c0;

    __shared__ float s_red[BLK / 32];

    float acc;
    if (chunk == 0)                acc = run_chunk<true,  false>(xb, yb, 0, lane);
    else if (chunk == NCHUNK - 1)  acc = run_chunk<false, true >(xb, yb, row0, lane);
    else                           acc = run_chunk<false, false>(xb, yb, row0, lane);

#pragma unroll
    for (int off = 16; off; off >>= 1)
        acc += __shfl_xor_sync(0xffffffffu, acc, off);
    if (lane == 0) s_red[warp] = acc;
    __syncthreads();
    if (threadIdx.x == 0) {
        float ctot = 0.f;
#pragma unroll
        for (int w = 0; w < BLK / 32; w++) ctot += s_red[w];
        atomicAdd(&g_acc, (double)ctot);
        __threadfence();
        int old = atomicAdd(&g_count, 1);
        if (old == NCTA - 1) {
            double total = g_acc;
            out[0] = (float)(1.0 - total * (1.0 / ((double)Bb * Hh * Ww)));
            g_acc = 0.0;
            g_count = 0;
        }
    }
}

extern "C" void kernel_launch(void* const* d_in, const int* in_sizes, int n_in,
                              void* d_out, int out_size) {
    const float* x = (const float*)d_in[0];
    const float* y = (const float*)d_in[1];
    (void)in_sizes; (void)n_in; (void)out_size;
    k_ssim<<<NCTA, BLK>>>(x, y, (float*)d_out);
}

// round 7
// speedup vs baseline: 1.7729x; 1.1651x over previous
#include <cuda_runtime.h>

// SSIM loss, B=64, 1x512x512 fp32, 11x11 box filter, zero padding.
// R6: R5 hit the 255-reg cap and spilled (L1 41.6->56.9%). Fixes:
//  - leave-row prefetch buffer dropped (-32 regs); leave LDGs issued at top
//    of iteration, consumed after the enter phase (latency mostly covered).
//  - paired divides: one __fdividef per (A,B) pixel pair -> 8 MUFU rcp/row.
//  - enter-row prefetch + split sliding chains kept from R5.
// Shape: 256 CTAs x 128 thr, CHUNK=32, 16 cols/lane.

typedef unsigned long long u64;

__device__ __forceinline__ u64 pk2(float lo, float hi) {
    u64 r; asm("mov.b64 %0, {%1, %2};" : "=l"(r) : "f"(lo), "f"(hi)); return r;
}
__device__ __forceinline__ void upk2(u64 v, float& lo, float& hi) {
    asm("mov.b64 {%0, %1}, %2;" : "=f"(lo), "=f"(hi) : "l"(v));
}
__device__ __forceinline__ u64 add2(u64 a, u64 b) {
    u64 r; asm("add.rn.f32x2 %0, %1, %2;" : "=l"(r) : "l"(a), "l"(b)); return r;
}
__device__ __forceinline__ u64 mul2(u64 a, u64 b) {
    u64 r; asm("mul.rn.f32x2 %0, %1, %2;" : "=l"(r) : "l"(a), "l"(b)); return r;
}
__device__ __forceinline__ u64 fma2(u64 a, u64 b, u64 c) {
    u64 r; asm("fma.rn.f32x2 %0, %1, %2, %3;" : "=l"(r) : "l"(a), "l"(b), "l"(c)); return r;
}

namespace {
constexpr int Hh = 512;
constexpr int Ww = 512;
constexpr int Bb = 64;
constexpr int CHUNK = 32;
constexpr int NCHUNK = Hh / CHUNK;           // 16
constexpr int BLK = 128;                     // 4 warps/CTA
constexpr int NCTA = Bb * NCHUNK * 32 / BLK; // 256
constexpr float C1S = 0.0001f * 14641.0f;    // 1.4641
constexpr float C2S = 0.0009f * 14641.0f;    // 13.1769
}

__device__ double g_acc;
__device__ int    g_count;

template<bool TOP, bool BOT>
__device__ __forceinline__ float run_chunk(const float* __restrict__ xb,
                                           const float* __restrict__ yb,
                                           const int row0, const int lane) {
    const u64 KN1 = pk2(-1.f, -1.f);
    const float lmaskf = (lane == 0)  ? 0.f : 1.f;
    const float rmaskf = (lane == 31) ? 0.f : 1.f;
    const u64 lmask2 = pk2(lmaskf, lmaskf);
    const u64 rmask2 = pk2(rmaskf, rmaskf);

    u64 vab[16], vsq[16];
    float vxy[16];
#pragma unroll
    for (int k = 0; k < 16; k++) { vab[k] = 0ull; vsq[k] = 0ull; vxy[k] = 0.f; }

    float acc = 0.f;
    float4 pex0, pex1, pex2, pex3, pey0, pey1, pey2, pey3;   // prefetched enter row

#define VENT(k, xs, ys) do { float _x=(xs), _y=(ys); u64 _p=pk2(_x,_y); \
    vab[k]=add2(vab[k],_p); vsq[k]=fma2(_p,_p,vsq[k]); vxy[k]=fmaf(_x,_y,vxy[k]); } while(0)
#define VLEA(k, xs, ys) do { float _x=(xs), _y=(ys); u64 _p=pk2(_x,_y); u64 _n=mul2(_p,KN1); \
    vab[k]=add2(vab[k],_n); vsq[k]=fma2(_n,_p,vsq[k]); vxy[k]=fmaf(-_x,_y,vxy[k]); } while(0)
#define ROW_APPLY(OP) \
    OP(0,a0.x,b0.x);  OP(1,a0.y,b0.y);  OP(2,a0.z,b0.z);  OP(3,a0.w,b0.w); \
    OP(4,a1.x,b1.x);  OP(5,a1.y,b1.y);  OP(6,a1.z,b1.z);  OP(7,a1.w,b1.w); \
    OP(8,a2.x,b2.x);  OP(9,a2.y,b2.y);  OP(10,a2.z,b2.z); OP(11,a2.w,b2.w); \
    OP(12,a3.x,b3.x); OP(13,a3.y,b3.y); OP(14,a3.z,b3.z); OP(15,a3.w,b3.w);

#define ENTER_DIRECT(r) do { \
    const float4* xr = reinterpret_cast<const float4*>(xb + (r) * Ww); \
    const float4* yr = reinterpret_cast<const float4*>(yb + (r) * Ww); \
    float4 a0 = xr[0], a1 = xr[1], a2 = xr[2], a3 = xr[3]; \
    float4 b0 = yr[0], b1 = yr[1], b2 = yr[2], b3 = yr[3]; \
    ROW_APPLY(VENT) } while(0)

#define PREF_E(r) do { \
    const float4* _xr = reinterpret_cast<const float4*>(xb + (r) * Ww); \
    const float4* _yr = reinterpret_cast<const float4*>(yb + (r) * Ww); \
    pex0=_xr[0]; pex1=_xr[1]; pex2=_xr[2]; pex3=_xr[3]; \
    pey0=_yr[0]; pey1=_yr[1]; pey2=_yr[2]; pey3=_yr[3]; } while(0)

#define SC4(v, m) do { (v).x*=(m); (v).y*=(m); (v).z*=(m); (v).w*=(m); } while(0)

#define HIN2(L, V) add2(add2(add2(add2(L[0],L[1]), add2(L[2],L[3])), \
                             add2(add2(L[4],V[0]), add2(V[1],V[2]))), \
                        add2(add2(V[3],V[4]), V[5]))
#define SUM11P(V) add2(add2(add2(add2(V[3],V[4]), add2(V[5],V[6])), \
                            add2(add2(V[7],V[8]), add2(V[9],V[10]))), \
                       add2(add2(V[11],V[12]), V[13]))
#define HADD(A, R, jj) (((jj) + 6 <= 15) ? A[((jj) + 6) & 15] : R[(((jj) - 10) < 0) ? 0 : ((jj) - 10)])
#define HSUB(A, L, jj) (((jj) >= 5) ? A[((jj) - 5) & 15] : L[((jj) < 5) ? (jj) : 4])

    // numerator/denominator of one pixel from its window sums
#define ND(sab, ssq, sxy, nv, dv) do { \
    float sx, sy, sxx, syy; \
    upk2(sab, sx, sy); \
    upk2(ssq, sxx, syy); \
    float pxy  = sx * sy; \
    float m2   = fmaf(sx, sx, sy * sy); \
    float esum = sxx + syy; \
    nv = fmaf(2.f, pxy, C1S) * fmaf(242.f, sxy, fmaf(-2.f, pxy, C2S)); \
    dv = (m2 + C1S) * fmaf(121.f, esum, C2S - m2); } while(0)

#define EPI() do { \
    u64 lab[5], lsq[5], rab[5], rsq[5]; \
    float lxy[5], rxy[5]; \
    _Pragma("unroll") \
    for (int j = 0; j < 5; j++) { \
        lab[j] = mul2(__shfl_up_sync(0xffffffffu, vab[11 + j], 1), lmask2); \
        lsq[j] = mul2(__shfl_up_sync(0xffffffffu, vsq[11 + j], 1), lmask2); \
        lxy[j] = __shfl_up_sync(0xffffffffu, vxy[11 + j], 1) * lmaskf; \
        rab[j] = mul2(__shfl_down_sync(0xffffffffu, vab[j], 1), rmask2); \
        rsq[j] = mul2(__shfl_down_sync(0xffffffffu, vsq[j], 1), rmask2); \
        rxy[j] = __shfl_down_sync(0xffffffffu, vxy[j], 1) * rmaskf; \
    } \
    u64 sabA = HIN2(lab, vab); \
    u64 ssqA = HIN2(lsq, vsq); \
    float sxyA = ((lxy[0]+lxy[1]) + (lxy[2]+lxy[3])) + ((lxy[4]+vxy[0]) + (vxy[1]+vxy[2])) \
               + ((vxy[3]+vxy[4]) + vxy[5]); \
    u64 sabB = SUM11P(vab); \
    u64 ssqB = SUM11P(vsq); \
    float sxyB = ((vxy[3]+vxy[4]) + (vxy[5]+vxy[6])) + ((vxy[7]+vxy[8]) + (vxy[9]+vxy[10])) \
               + ((vxy[11]+vxy[12]) + vxy[13]); \
    _Pragma("unroll") \
    for (int j = 0; j < 8; j++) { \
        float nA, dA, nB, dB; \
        ND(sabA, ssqA, sxyA, nA, dA); \
        ND(sabB, ssqB, sxyB, nB, dB); \
        acc += __fdividef(fmaf(nA, dB, nB * dA), dA * dB); \
        if (j < 7) { \
            const int jB = j + 8; \
            sabA = add2(sabA, HADD(vab, rab, j)); \
            sabA = fma2(HSUB(vab, lab, j), KN1, sabA); \
            ssqA = add2(ssqA, HADD(vsq, rsq, j)); \
            ssqA = fma2(HSUB(vsq, lsq, j), KN1, ssqA); \
            sxyA += HADD(vxy, rxy, j) - HSUB(vxy, lxy, j); \
            sabB = add2(sabB, HADD(vab, rab, jB)); \
            sabB = fma2(HSUB(vab, lab, jB), KN1, sabB); \
            ssqB = add2(ssqB, HADD(vsq, rsq, jB)); \
            ssqB = fma2(HSUB(vsq, lsq, jB), KN1, ssqB); \
            sxyB += HADD(vxy, rxy, jB) - HSUB(vxy, lxy, jB); \
        } \
    } } while(0)

    // ---- warmup: rows row0-5 .. row0+4 (TOP skips negative rows) ----
    {
        const int w0 = TOP ? 5 : 0;
#pragma unroll
        for (int i = w0; i < 10; i++) ENTER_DIRECT(row0 - 5 + i);
    }

    // ---- first output row (ri = row0+5, no leave) ----
    ENTER_DIRECT(row0 + 5);
    PREF_E(row0 + 6);
    EPI();

    // ---- steady: 31 iterations, prefetched enter, direct leave ----
#pragma unroll 1
    for (int i = 0; i < CHUNK - 1; i++) {
        const int ri = row0 + 6 + i;
        const int lv = ri - 11;
        // issue leave-row loads first (consumed after the enter phase)
        float4 la0, la1, la2, la3, lb0, lb1, lb2, lb3;
        {
            const int lr = TOP ? ((lv < 0) ? 0 : lv) : lv;
            const float4* _xr = reinterpret_cast<const float4*>(xb + lr * Ww);
            const float4* _yr = reinterpret_cast<const float4*>(yb + lr * Ww);
            la0 = _xr[0]; la1 = _xr[1]; la2 = _xr[2]; la3 = _xr[3];
            lb0 = _yr[0]; lb1 = _yr[1]; lb2 = _yr[2]; lb3 = _yr[3];
        }
        {   // consume prefetched enter
            float4 a0 = pex0, a1 = pex1, a2 = pex2, a3 = pex3;
            float4 b0 = pey0, b1 = pey1, b2 = pey2, b3 = pey3;
            if (BOT) {
                const float em = (ri < Hh) ? 1.f : 0.f;
                SC4(a0, em); SC4(a1, em); SC4(a2, em); SC4(a3, em);
                SC4(b0, em); SC4(b1, em); SC4(b2, em); SC4(b3, em);
            }
            ROW_APPLY(VENT)
        }
        {   // prefetch next enter (clamped; garbage never consumed)
            int er = ri + 1; if (BOT && er > Hh - 1) er = Hh - 1;
            PREF_E(er);
        }
        {   // consume leave
            float4 a0 = la0, a1 = la1, a2 = la2, a3 = la3;
            float4 b0 = lb0, b1 = lb1, b2 = lb2, b3 = lb3;
            if (TOP) {
                const float lm = (lv >= 0) ? 1.f : 0.f;
                SC4(a0, lm); SC4(a1, lm); SC4(a2, lm); SC4(a3, lm);
                SC4(b0, lm); SC4(b1, lm); SC4(b2, lm); SC4(b3, lm);
            }
            ROW_APPLY(VLEA)
        }
        EPI();
    }

    return acc;

#undef VENT
#undef VLEA
#undef ROW_APPLY
#undef ENTER_DIRECT
#undef PREF_E
#undef SC4
#undef HIN2
#undef SUM11P
#undef HADD
#undef HSUB
#undef ND
#undef EPI
}

__global__ void __launch_bounds__(BLK)
k_ssim(const float* __restrict__ X, const float* __restrict__ Y, float* __restrict__ out) {
    const int warp  = threadIdx.x >> 5;
    const int lane  = threadIdx.x & 31;
    const int gwarp = blockIdx.x * (BLK / 32) + warp;
    const int batch = gwarp >> 4;              // / NCHUNK
    const int chunk = gwarp & (NCHUNK - 1);
    const int row0  = chunk * CHUNK;
    const int c0    = lane << 4;
    const float* xb = X + batch * (Hh * Ww) + c0;
    const float* yb = Y + batch * (Hh * Ww) + c0;

    __shared__ float s_red[BLK / 32];

    float acc;
    if (chunk == 0)                acc = run_chunk<true,  false>(xb, yb, 0, lane);
    else if (chunk == NCHUNK - 1)  acc = run_chunk<false, true >(xb, yb, row0, lane);
    else                           acc = run_chunk<false, false>(xb, yb, row0, lane);

#pragma unroll
    for (int off = 16; off; off >>= 1)
        acc += __shfl_xor_sync(0xffffffffu, acc, off);
    if (lane == 0) s_red[warp] = acc;
    __syncthreads();
    if (threadIdx.x == 0) {
        float ctot = 0.f;
#pragma unroll
        for (int w = 0; w < BLK / 32; w++) ctot += s_red[w];
        atomicAdd(&g_acc, (double)ctot);
        __threadfence();
        int old = atomicAdd(&g_count, 1);
        if (old == NCTA - 1) {
            double total = g_acc;
            out[0] = (float)(1.0 - total * (1.0 / ((double)Bb * Hh * Ww)));
            g_acc = 0.0;
            g_count = 0;
        }
    }
}

extern "C" void kernel_launch(void* const* d_in, const int* in_sizes, int n_in,
                              void* d_out, int out_size) {
    const float* x = (const float*)d_in[0];
    const float* y = (const float*)d_in[1];
    (void)in_sizes; (void)n_in; (void)out_size;
    k_ssim<<<NCTA, BLK>>>(x, y, (float*)d_out);
}

// round 8
// speedup vs baseline: 1.9515x; 1.1008x over previous
#include <cuda_runtime.h>

// SSIM loss, B=64, 1x512x512 fp32, 11x11 box filter, zero padding.
// R7: register-pressure cut in the epilogue (R6 still pinned at 255 regs,
// L1 52% = spill traffic). Dataflow: chain A (cols 0-7) only needs LEFT
// halos; chain B (cols 8-15) only needs RIGHT halos, one value per slide
// step -> shuffle them on demand (same shuffle count, ~6 transient regs
// instead of 25 held across the whole epilogue).
// Keeps: enter-row prefetch, paired divides, split chains, CHUNK=32,
// 16 cols/lane, 256 CTAs x 128 thr.

typedef unsigned long long u64;

__device__ __forceinline__ u64 pk2(float lo, float hi) {
    u64 r; asm("mov.b64 %0, {%1, %2};" : "=l"(r) : "f"(lo), "f"(hi)); return r;
}
__device__ __forceinline__ void upk2(u64 v, float& lo, float& hi) {
    asm("mov.b64 {%0, %1}, %2;" : "=f"(lo), "=f"(hi) : "l"(v));
}
__device__ __forceinline__ u64 add2(u64 a, u64 b) {
    u64 r; asm("add.rn.f32x2 %0, %1, %2;" : "=l"(r) : "l"(a), "l"(b)); return r;
}
__device__ __forceinline__ u64 mul2(u64 a, u64 b) {
    u64 r; asm("mul.rn.f32x2 %0, %1, %2;" : "=l"(r) : "l"(a), "l"(b)); return r;
}
__device__ __forceinline__ u64 fma2(u64 a, u64 b, u64 c) {
    u64 r; asm("fma.rn.f32x2 %0, %1, %2, %3;" : "=l"(r) : "l"(a), "l"(b), "l"(c)); return r;
}

namespace {
constexpr int Hh = 512;
constexpr int Ww = 512;
constexpr int Bb = 64;
constexpr int CHUNK = 32;
constexpr int NCHUNK = Hh / CHUNK;           // 16
constexpr int BLK = 128;                     // 4 warps/CTA
constexpr int NCTA = Bb * NCHUNK * 32 / BLK; // 256
constexpr float C1S = 0.0001f * 14641.0f;    // 1.4641
constexpr float C2S = 0.0009f * 14641.0f;    // 13.1769
}

__device__ double g_acc;
__device__ int    g_count;

template<bool TOP, bool BOT>
__device__ __forceinline__ float run_chunk(const float* __restrict__ xb,
                                           const float* __restrict__ yb,
                                           const int row0, const int lane) {
    const u64 KN1 = pk2(-1.f, -1.f);
    const float lmaskf = (lane == 0)  ? 0.f : 1.f;
    const float rmaskf = (lane == 31) ? 0.f : 1.f;
    const u64 lmask2 = pk2(lmaskf, lmaskf);
    const u64 rmask2 = pk2(rmaskf, rmaskf);

    u64 vab[16], vsq[16];
    float vxy[16];
#pragma unroll
    for (int k = 0; k < 16; k++) { vab[k] = 0ull; vsq[k] = 0ull; vxy[k] = 0.f; }

    float acc = 0.f;
    float4 pex0, pex1, pex2, pex3, pey0, pey1, pey2, pey3;   // prefetched enter row

#define VENT(k, xs, ys) do { float _x=(xs), _y=(ys); u64 _p=pk2(_x,_y); \
    vab[k]=add2(vab[k],_p); vsq[k]=fma2(_p,_p,vsq[k]); vxy[k]=fmaf(_x,_y,vxy[k]); } while(0)
#define VLEA(k, xs, ys) do { float _x=(xs), _y=(ys); u64 _p=pk2(_x,_y); u64 _n=mul2(_p,KN1); \
    vab[k]=add2(vab[k],_n); vsq[k]=fma2(_n,_p,vsq[k]); vxy[k]=fmaf(-_x,_y,vxy[k]); } while(0)
#define ROW_APPLY(OP) \
    OP(0,a0.x,b0.x);  OP(1,a0.y,b0.y);  OP(2,a0.z,b0.z);  OP(3,a0.w,b0.w); \
    OP(4,a1.x,b1.x);  OP(5,a1.y,b1.y);  OP(6,a1.z,b1.z);  OP(7,a1.w,b1.w); \
    OP(8,a2.x,b2.x);  OP(9,a2.y,b2.y);  OP(10,a2.z,b2.z); OP(11,a2.w,b2.w); \
    OP(12,a3.x,b3.x); OP(13,a3.y,b3.y); OP(14,a3.z,b3.z); OP(15,a3.w,b3.w);

#define ENTER_DIRECT(r) do { \
    const float4* xr = reinterpret_cast<const float4*>(xb + (r) * Ww); \
    const float4* yr = reinterpret_cast<const float4*>(yb + (r) * Ww); \
    float4 a0 = xr[0], a1 = xr[1], a2 = xr[2], a3 = xr[3]; \
    float4 b0 = yr[0], b1 = yr[1], b2 = yr[2], b3 = yr[3]; \
    ROW_APPLY(VENT) } while(0)

#define PREF_E(r) do { \
    const float4* _xr = reinterpret_cast<const float4*>(xb + (r) * Ww); \
    const float4* _yr = reinterpret_cast<const float4*>(yb + (r) * Ww); \
    pex0=_xr[0]; pex1=_xr[1]; pex2=_xr[2]; pex3=_xr[3]; \
    pey0=_yr[0]; pey1=_yr[1]; pey2=_yr[2]; pey3=_yr[3]; } while(0)

#define SC4(v, m) do { (v).x*=(m); (v).y*=(m); (v).z*=(m); (v).w*=(m); } while(0)

    // chain A init: left halos l[0..4] + v[0..5]
#define HIN2(L, V) add2(add2(add2(add2(L[0],L[1]), add2(L[2],L[3])), \
                             add2(add2(L[4],V[0]), add2(V[1],V[2]))), \
                        add2(add2(V[3],V[4]), V[5]))
    // chain B init: v[3..13]
#define SUM11P(V) add2(add2(add2(add2(V[3],V[4]), add2(V[5],V[6])), \
                            add2(add2(V[7],V[8]), add2(V[9],V[10]))), \
                       add2(add2(V[11],V[12]), V[13]))

#define ND(sab, ssq, sxy, nv, dv) do { \
    float sx, sy, sxx, syy; \
    upk2(sab, sx, sy); \
    upk2(ssq, sxx, syy); \
    float pxy  = sx * sy; \
    float m2   = fmaf(sx, sx, sy * sy); \
    float esum = sxx + syy; \
    nv = fmaf(2.f, pxy, C1S) * fmaf(242.f, sxy, fmaf(-2.f, pxy, C2S)); \
    dv = (m2 + C1S) * fmaf(121.f, esum, C2S - m2); } while(0)

#define EPI() do { \
    /* left halos only (chain A init + its subtract steps 0..4) */ \
    u64 lab[5], lsq[5]; \
    float lxy[5]; \
    _Pragma("unroll") \
    for (int j = 0; j < 5; j++) { \
        lab[j] = mul2(__shfl_up_sync(0xffffffffu, vab[11 + j], 1), lmask2); \
        lsq[j] = mul2(__shfl_up_sync(0xffffffffu, vsq[11 + j], 1), lmask2); \
        lxy[j] = __shfl_up_sync(0xffffffffu, vxy[11 + j], 1) * lmaskf; \
    } \
    u64 sabA = HIN2(lab, vab); \
    u64 ssqA = HIN2(lsq, vsq); \
    float sxyA = ((lxy[0]+lxy[1]) + (lxy[2]+lxy[3])) + ((lxy[4]+vxy[0]) + (vxy[1]+vxy[2])) \
               + ((vxy[3]+vxy[4]) + vxy[5]); \
    u64 sabB = SUM11P(vab); \
    u64 ssqB = SUM11P(vsq); \
    float sxyB = ((vxy[3]+vxy[4]) + (vxy[5]+vxy[6])) + ((vxy[7]+vxy[8]) + (vxy[9]+vxy[10])) \
               + ((vxy[11]+vxy[12]) + vxy[13]); \
    _Pragma("unroll") \
    for (int j = 0; j < 8; j++) { \
        float nA, dA, nB, dB; \
        ND(sabA, ssqA, sxyA, nA, dA); \
        ND(sabB, ssqB, sxyB, nB, dB); \
        acc += __fdividef(fmaf(nA, dB, nB * dA), dA * dB); \
        if (j < 7) { \
            /* chain A: add v[j+6] (interior), sub lab[j] (j<5) / v[j-5] */ \
            sabA = add2(sabA, vab[j + 6]); \
            ssqA = add2(ssqA, vsq[j + 6]); \
            sxyA += vxy[j + 6]; \
            if (j < 5) { \
                sabA = fma2(lab[j], KN1, sabA); \
                ssqA = fma2(lsq[j], KN1, ssqA); \
                sxyA -= lxy[j]; \
            } else { \
                sabA = fma2(vab[j - 5], KN1, sabA); \
                ssqA = fma2(vsq[j - 5], KN1, ssqA); \
                sxyA -= vxy[j - 5]; \
            } \
            /* chain B: add v[14+j] (j<2) / on-demand right halo, sub v[j+3] */ \
            u64 hb_ab, hb_sq; \
            float hb_xy; \
            if (j < 2) { \
                hb_ab = vab[14 + j]; hb_sq = vsq[14 + j]; hb_xy = vxy[14 + j]; \
            } else { \
                hb_ab = mul2(__shfl_down_sync(0xffffffffu, vab[j - 2], 1), rmask2); \
                hb_sq = mul2(__shfl_down_sync(0xffffffffu, vsq[j - 2], 1), rmask2); \
                hb_xy = __shfl_down_sync(0xffffffffu, vxy[j - 2], 1) * rmaskf; \
            } \
            sabB = add2(sabB, hb_ab); \
            sabB = fma2(vab[j + 3], KN1, sabB); \
            ssqB = add2(ssqB, hb_sq); \
            ssqB = fma2(vsq[j + 3], KN1, ssqB); \
            sxyB += hb_xy - vxy[j + 3]; \
        } \
    } } while(0)

    // ---- warmup: rows row0-5 .. row0+4 (TOP skips negative rows) ----
    {
        const int w0 = TOP ? 5 : 0;
#pragma unroll
        for (int i = w0; i < 10; i++) ENTER_DIRECT(row0 - 5 + i);
    }

    // ---- first output row (ri = row0+5, no leave) ----
    ENTER_DIRECT(row0 + 5);
    PREF_E(row0 + 6);
    EPI();

    // ---- steady: 31 iterations, prefetched enter, early-issued leave ----
#pragma unroll 1
    for (int i = 0; i < CHUNK - 1; i++) {
        const int ri = row0 + 6 + i;
        const int lv = ri - 11;
        // issue leave-row loads first (consumed after the enter phase)
        float4 la0, la1, la2, la3, lb0, lb1, lb2, lb3;
        {
            const int lr = TOP ? ((lv < 0) ? 0 : lv) : lv;
            const float4* _xr = reinterpret_cast<const float4*>(xb + lr * Ww);
            const float4* _yr = reinterpret_cast<const float4*>(yb + lr * Ww);
            la0 = _xr[0]; la1 = _xr[1]; la2 = _xr[2]; la3 = _xr[3];
            lb0 = _yr[0]; lb1 = _yr[1]; lb2 = _yr[2]; lb3 = _yr[3];
        }
        {   // consume prefetched enter
            float4 a0 = pex0, a1 = pex1, a2 = pex2, a3 = pex3;
            float4 b0 = pey0, b1 = pey1, b2 = pey2, b3 = pey3;
            if (BOT) {
                const float em = (ri < Hh) ? 1.f : 0.f;
                SC4(a0, em); SC4(a1, em); SC4(a2, em); SC4(a3, em);
                SC4(b0, em); SC4(b1, em); SC4(b2, em); SC4(b3, em);
            }
            ROW_APPLY(VENT)
        }
        {   // prefetch next enter (clamped; garbage never consumed)
            int er = ri + 1; if (BOT && er > Hh - 1) er = Hh - 1;
            PREF_E(er);
        }
        {   // consume leave
            float4 a0 = la0, a1 = la1, a2 = la2, a3 = la3;
            float4 b0 = lb0, b1 = lb1, b2 = lb2, b3 = lb3;
            if (TOP) {
                const float lm = (lv >= 0) ? 1.f : 0.f;
                SC4(a0, lm); SC4(a1, lm); SC4(a2, lm); SC4(a3, lm);
                SC4(b0, lm); SC4(b1, lm); SC4(b2, lm); SC4(b3, lm);
            }
            ROW_APPLY(VLEA)
        }
        EPI();
    }

    return acc;

#undef VENT
#undef VLEA
#undef ROW_APPLY
#undef ENTER_DIRECT
#undef PREF_E
#undef SC4
#undef HIN2
#undef SUM11P
#undef ND
#undef EPI
}

__global__ void __launch_bounds__(BLK)
k_ssim(const float* __restrict__ X, const float* __restrict__ Y, float* __restrict__ out) {
    const int warp  = threadIdx.x >> 5;
    const int lane  = threadIdx.x & 31;
    const int gwarp = blockIdx.x * (BLK / 32) + warp;
    const int batch = gwarp >> 4;              // / NCHUNK
    const int chunk = gwarp & (NCHUNK - 1);
    const int row0  = chunk * CHUNK;
    const int c0    = lane << 4;
    const float* xb = X + batch * (Hh * Ww) + c0;
    const float* yb = Y + batch * (Hh * Ww) + c0;

    __shared__ float s_red[BLK / 32];

    float acc;
    if (chunk == 0)                acc = run_chunk<true,  false>(xb, yb, 0, lane);
    else if (chunk == NCHUNK - 1)  acc = run_chunk<false, true >(xb, yb, row0, lane);
    else                           acc = run_chunk<false, false>(xb, yb, row0, lane);

#pragma unroll
    for (int off = 16; off; off >>= 1)
        acc += __shfl_xor_sync(0xffffffffu, acc, off);
    if (lane == 0) s_red[warp] = acc;
    __syncthreads();
    if (threadIdx.x == 0) {
        float ctot = 0.f;
#pragma unroll
        for (int w = 0; w < BLK / 32; w++) ctot += s_red[w];
        atomicAdd(&g_acc, (double)ctot);
        __threadfence();
        int old = atomicAdd(&g_count, 1);
        if (old == NCTA - 1) {
            double total = g_acc;
            out[0] = (float)(1.0 - total * (1.0 / ((double)Bb * Hh * Ww)));
            g_acc = 0.0;
            g_count = 0;
        }
    }
}

extern "C" void kernel_launch(void* const* d_in, const int* in_sizes, int n_in,
                              void* d_out, int out_size) {
    const float* x = (const float*)d_in[0];
    const float* y = (const float*)d_in[1];
    (void)in_sizes; (void)n_in; (void)out_size;
    k_ssim<<<NCTA, BLK>>>(x, y, (float*)d_out);
}